// round 6
// baseline (speedup 1.0000x reference)
#include <cuda_runtime.h>
#include <math.h>

// Problem constants (match reference)
#define N_INPUTSC 2048
#define UNITSC    2048
#define LC        8
#define FANINC    4096
#define TOTALC    18432

#define KC      512          // k-chunks (partial-sum depth), 8 rows each
#define KCH     8            // rows per chunk
#define JT      4            // column tiles of 512
#define NTILES  (KC * JT)    // 2048 tiles per layer

// Persistent scratch (allocation-free rule: __device__ globals)
__device__ float g_partial[2][KC * UNITSC];  // ping-pong partials, 4MB each
__device__ float g_outputs[TOTALC];          // materialized state vector
__device__ float g_gather[FANINC];           // gathered input for current layer

// Warp-shuffle reduce of one column of the previous layer's partials.
__device__ __forceinline__ float warp_reduce_col(const float* __restrict__ P,
                                                 int u, int lane) {
    float s = 0.f;
#pragma unroll
    for (int j = 0; j < 16; ++j)
        s += P[(lane + 32 * j) * UNITSC + u];
#pragma unroll
    for (int off = 16; off; off >>= 1)
        s += __shfl_xor_sync(0xffffffffu, s, off);
    return s;
}

// ---------------------------------------------------------------------------
// prep: one warp per element. Warps 0..2047 materialize slice `layer`
// (layer==LC: write final result to `out` instead); warps 2048..6143 build
// the gathered vector g_gather for this layer's node_inds.
// ---------------------------------------------------------------------------
__global__ __launch_bounds__(256) void prep_kernel(
    int layer,
    const float* __restrict__ x,
    const int*   __restrict__ node_inds,
    const float* __restrict__ bs,
    float*       __restrict__ out)
{
    int gtid = blockIdx.x * 256 + threadIdx.x;
    int wid  = gtid >> 5;
    int lane = gtid & 31;
    const float* Pprev = g_partial[(layer + 1) & 1];
    const float* bprev = bs + (layer - 1) * UNITSC;
    const int base  = layer << 11;
    const int limit = base + UNITSC;

    if (wid < UNITSC) {
        int u = wid;
        float o;
        if (layer == 0) {
            o = x[u];
        } else {
            o = tanhf(warp_reduce_col(Pprev, u, lane) + bprev[u]);
        }
        if (lane == 0) {
            if (layer == LC) out[u]              = o;
            else             g_outputs[base + u] = o;
        }
    } else {
        int k = wid - UNITSC;   // only launched when layer < LC
        int idx = node_inds[layer * FANINC + k];
        float v = 0.f;
        if (idx < base) {
            v = g_outputs[idx];           // older slice, already materialized
        } else if (idx < limit) {
            int u = idx - base;           // latest slice: recompute
            if (layer == 0) v = x[u];
            else            v = tanhf(warp_reduce_col(Pprev, u, lane) + bprev[u]);
        }
        if (lane == 0) g_gather[k] = v;
    }
}

// ---------------------------------------------------------------------------
// gemv: barrier-free W streaming. Grid = 2048 blocks x 128 threads.
// Block t: kc = t>>2 (8-row chunk), jt = t&3 (512-col tile).
// Thread: 4 cols (float4) x 8 rows = 8 independent LDG.128 + 8 broadcast
// g_gather loads, 32 FMA, one private float4 partial store. No smem/sync.
// ---------------------------------------------------------------------------
__global__ __launch_bounds__(128) void gemv_kernel(
    int layer,
    const float* __restrict__ Ws)
{
    float* Pcur = g_partial[layer & 1];
    const int t  = blockIdx.x;
    const int kc = t >> 2;
    const int jt = t & 3;
    const int j0 = jt * 512 + threadIdx.x * 4;
    const int kb = kc * KCH;

    const float* W = Ws + ((size_t)layer * FANINC + kb) * UNITSC + j0;
    const float* g = g_gather + kb;

    float gv[KCH];
#pragma unroll
    for (int r = 0; r < KCH; ++r) gv[r] = g[r];

    float ax = 0.f, ay = 0.f, az = 0.f, aw = 0.f;
#pragma unroll
    for (int r = 0; r < KCH; ++r) {
        float4 w = *reinterpret_cast<const float4*>(W + (size_t)r * UNITSC);
        ax = fmaf(gv[r], w.x, ax);
        ay = fmaf(gv[r], w.y, ay);
        az = fmaf(gv[r], w.z, az);
        aw = fmaf(gv[r], w.w, aw);
    }
    *reinterpret_cast<float4*>(Pcur + kc * UNITSC + j0) =
        make_float4(ax, ay, az, aw);
}

extern "C" void kernel_launch(void* const* d_in, const int* in_sizes, int n_in,
                              void* d_out, int out_size) {
    const float* x  = (const float*)d_in[0];   // [2048] f32
    const int*   ni = (const int*)d_in[1];     // [8, 4096] i32
    const float* Ws = (const float*)d_in[2];   // [8, 4096, 2048] f32
    const float* bs = (const float*)d_in[3];   // [8, 2048] f32
    float* out = (float*)d_out;                // [2048] f32

    for (int i = 0; i < LC; ++i) {
        prep_kernel<<<(UNITSC + FANINC) / 8, 256>>>(i, x, ni, bs, out);
        gemv_kernel<<<NTILES, 128>>>(i, Ws);
    }
    // Final "prep": materialize layer-8 output straight into d_out.
    prep_kernel<<<UNITSC / 8, 256>>>(LC, x, ni, bs, out);
}

// round 7
// speedup vs baseline: 1.3445x; 1.3445x over previous
#include <cuda_runtime.h>
#include <math.h>

// Problem constants (match reference)
#define N_INPUTSC 2048
#define UNITSC    2048
#define LC        8
#define FANINC    4096
#define TOTALC    18432

#define KC      256          // k-chunks (partial-sum depth)
#define KCH     16           // rows per chunk
#define JT      4            // column tiles of 512
#define NTILES  (KC * JT)    // 1024 gemv tiles per layer

// Persistent scratch (allocation-free rule: __device__ globals)
__device__ float g_partial[2][KC * UNITSC];  // ping-pong partials, 2MB each
__device__ float g_outputs[TOTALC];          // materialized state vector

// ---------------------------------------------------------------------------
// reduce: materialize slice `layer` = tanh(colsum(prev partials) + b) (or x
// for layer 0; or d_out for layer==LC). Fully coalesced: thread-per-column,
// warp lanes = consecutive columns. Block = 256 thr as (64 cols x 4 kgroups).
// Grid = 32 blocks. Traffic = exactly KC*2048*4 = 2MB from L2.
// ---------------------------------------------------------------------------
__global__ __launch_bounds__(256) void reduce_kernel(
    int layer,
    const float* __restrict__ x,
    const float* __restrict__ bs,
    float*       __restrict__ out)
{
    const int u  = blockIdx.x * 64 + (threadIdx.x & 63);   // column 0..2047
    const int g  = threadIdx.x >> 6;                        // k-group 0..3
    const int base = layer << 11;

    if (layer == 0) {
        if (g == 0) g_outputs[u] = x[u];
        return;
    }

    const float* P = g_partial[(layer + 1) & 1] + u;        // prev partials
    float s0 = 0.f, s1 = 0.f;
#pragma unroll 8
    for (int j = 0; j < KC / 4; j += 2) {
        s0 += P[(size_t)(g * (KC / 4) + j)     * UNITSC];
        s1 += P[(size_t)(g * (KC / 4) + j + 1) * UNITSC];
    }
    __shared__ float sred[4][64];
    sred[g][threadIdx.x & 63] = s0 + s1;
    __syncthreads();
    if (g == 0) {
        float s = sred[0][u & 63] + sred[1][u & 63]
                + sred[2][u & 63] + sred[3][u & 63];
        float o = tanhf(s + bs[(layer - 1) * UNITSC + u]);
        if (layer == LC) out[u]              = o;
        else             g_outputs[base + u] = o;
    }
}

// ---------------------------------------------------------------------------
// gemv: W streaming with forced MLP=16. Grid = 1024 blocks x 128 threads.
// Block t: kc = t>>2 (16-row chunk), jt = t&3 (512-col tile).
// Prologue: 16 threads gather this chunk's inputs from g_outputs (masked by
// limit so unwritten future slices read as 0). Then each thread loads 16
// independent LDG.128 (front-batched into w[]) and does 64 FMA.
// Barrier-free epilogue: private float4 partial store.
// ---------------------------------------------------------------------------
__global__ __launch_bounds__(128) void gemv_kernel(
    int layer,
    const int*   __restrict__ node_inds,
    const float* __restrict__ Ws)
{
    float* Pcur = g_partial[layer & 1];
    const int t   = blockIdx.x;
    const int kc  = t >> 2;
    const int jt  = t & 3;
    const int tid = threadIdx.x;
    const int limit = (layer + 1) << 11;

    __shared__ float sg[KCH];
    if (tid < KCH) {
        int idx = node_inds[layer * FANINC + kc * KCH + tid];
        sg[tid] = (idx < limit) ? g_outputs[idx] : 0.f;
    }
    __syncthreads();

    const int j0 = jt * 512 + tid * 4;
    const float* W = Ws + ((size_t)layer * FANINC + kc * KCH) * UNITSC + j0;

    // Front-batched loads: 16 independent LDG.128 in flight.
    float4 w[KCH];
#pragma unroll
    for (int r = 0; r < KCH; ++r)
        w[r] = *reinterpret_cast<const float4*>(W + (size_t)r * UNITSC);

    float gv[KCH];
#pragma unroll
    for (int r = 0; r < KCH; ++r) gv[r] = sg[r];

    float ax = 0.f, ay = 0.f, az = 0.f, aw = 0.f;
#pragma unroll
    for (int r = 0; r < KCH; ++r) {
        ax = fmaf(gv[r], w[r].x, ax);
        ay = fmaf(gv[r], w[r].y, ay);
        az = fmaf(gv[r], w[r].z, az);
        aw = fmaf(gv[r], w[r].w, aw);
    }
    *reinterpret_cast<float4*>(Pcur + kc * UNITSC + j0) =
        make_float4(ax, ay, az, aw);
}

extern "C" void kernel_launch(void* const* d_in, const int* in_sizes, int n_in,
                              void* d_out, int out_size) {
    const float* x  = (const float*)d_in[0];   // [2048] f32
    const int*   ni = (const int*)d_in[1];     // [8, 4096] i32
    const float* Ws = (const float*)d_in[2];   // [8, 4096, 2048] f32
    const float* bs = (const float*)d_in[3];   // [8, 2048] f32
    float* out = (float*)d_out;                // [2048] f32

    for (int i = 0; i < LC; ++i) {
        reduce_kernel<<<32, 256>>>(i, x, bs, out);     // materialize slice i
        gemv_kernel<<<NTILES, 128>>>(i, ni, Ws);       // partials for layer i
    }
    reduce_kernel<<<32, 256>>>(LC, x, bs, out);        // final output
}

// round 8
// speedup vs baseline: 1.3737x; 1.0217x over previous
#include <cuda_runtime.h>
#include <math.h>
#include <stdint.h>

// Problem constants (match reference)
#define N_INPUTSC 2048
#define UNITSC    2048
#define LC        8
#define FANINC    4096
#define TOTALC    18432

#define KC      256          // k-chunks (partial-sum depth)
#define KCH     16           // rows per chunk
#define JT      4            // column tiles of 512
#define NTILES  (KC * JT)    // 1024 gemv tiles per layer

// Persistent scratch (allocation-free rule: __device__ globals)
__device__ float g_partial[2][KC * UNITSC];  // ping-pong partials, 2MB each
__device__ float g_outputs[TOTALC];          // materialized state vector

// ---------------------------------------------------------------------------
// reduce: materialize slice `layer` = tanh(colsum(prev partials) + b) (or x
// for layer 0; or d_out for layer==LC). Fully coalesced: thread-per-column.
// Block = 256 thr as (64 cols x 4 kgroups). Grid = 32 blocks.
// ---------------------------------------------------------------------------
__global__ __launch_bounds__(256) void reduce_kernel(
    int layer,
    const float* __restrict__ x,
    const float* __restrict__ bs,
    float*       __restrict__ out)
{
    const int u  = blockIdx.x * 64 + (threadIdx.x & 63);   // column 0..2047
    const int g  = threadIdx.x >> 6;                        // k-group 0..3
    const int base = layer << 11;

    if (layer == 0) {
        if (g == 0) g_outputs[u] = x[u];
        return;
    }

    const float* P = g_partial[(layer + 1) & 1] + u;        // prev partials
    float s0 = 0.f, s1 = 0.f;
#pragma unroll 8
    for (int j = 0; j < KC / 4; j += 2) {
        s0 += P[(size_t)(g * (KC / 4) + j)     * UNITSC];
        s1 += P[(size_t)(g * (KC / 4) + j + 1) * UNITSC];
    }
    __shared__ float sred[4][64];
    sred[g][threadIdx.x & 63] = s0 + s1;
    __syncthreads();
    if (g == 0) {
        float s = sred[0][u & 63] + sred[1][u & 63]
                + sred[2][u & 63] + sred[3][u & 63];
        float o = tanhf(s + bs[(layer - 1) * UNITSC + u]);
        if (layer == LC) out[u]              = o;
        else             g_outputs[base + u] = o;
    }
}

// ---------------------------------------------------------------------------
// gemv: cp.async-staged W streaming. Grid = 1024 blocks x 128 threads.
// Block t: kc = t>>2 (16-row chunk), jt = t&3 (512-col tile).
// Stage the full 16x512 W tile (32KB) into smem with 2048 in-flight
// cp.async.cg ops (no register cost), overlap the node_inds gather with the
// copy, then FMA from smem. Barrier-free epilogue: private float4 store.
// ---------------------------------------------------------------------------
__global__ __launch_bounds__(128) void gemv_kernel(
    int layer,
    const int*   __restrict__ node_inds,
    const float* __restrict__ Ws)
{
    __shared__ float tile[KCH * 512];
    __shared__ float sg[KCH];

    float* Pcur = g_partial[layer & 1];
    const int t   = blockIdx.x;
    const int kc  = t >> 2;
    const int jt  = t & 3;
    const int tid = threadIdx.x;
    const int limit = (layer + 1) << 11;

    const float* W = Ws + ((size_t)layer * FANINC + kc * KCH) * UNITSC + jt * 512;

    // Issue 16 cp.async.cg (16B each) per thread: thread copies row i,
    // bytes [tid*16, tid*16+16). All 2048 block ops in flight at once.
    uint32_t sbase = (uint32_t)__cvta_generic_to_shared(tile);
#pragma unroll
    for (int i = 0; i < KCH; ++i) {
        uint32_t dst = sbase + (uint32_t)((i * 512 + tid * 4) * 4);
        const float* src = W + (size_t)i * UNITSC + tid * 4;
        asm volatile("cp.async.cg.shared.global [%0], [%1], 16;\n"
                     :: "r"(dst), "l"(src));
    }
    asm volatile("cp.async.commit_group;\n");

    // Overlap: gather this chunk's 16 inputs while the tile streams in.
    if (tid < KCH) {
        int idx = node_inds[layer * FANINC + kc * KCH + tid];
        sg[tid] = (idx < limit) ? g_outputs[idx] : 0.f;
    }

    asm volatile("cp.async.wait_group 0;\n");
    __syncthreads();

    const int j0 = jt * 512 + tid * 4;
    float ax = 0.f, ay = 0.f, az = 0.f, aw = 0.f;
#pragma unroll
    for (int r = 0; r < KCH; ++r) {
        float gk = sg[r];
        float4 w = *reinterpret_cast<const float4*>(tile + r * 512 + tid * 4);
        ax = fmaf(gk, w.x, ax);
        ay = fmaf(gk, w.y, ay);
        az = fmaf(gk, w.z, az);
        aw = fmaf(gk, w.w, aw);
    }
    *reinterpret_cast<float4*>(Pcur + kc * UNITSC + j0) =
        make_float4(ax, ay, az, aw);
}

extern "C" void kernel_launch(void* const* d_in, const int* in_sizes, int n_in,
                              void* d_out, int out_size) {
    const float* x  = (const float*)d_in[0];   // [2048] f32
    const int*   ni = (const int*)d_in[1];     // [8, 4096] i32
    const float* Ws = (const float*)d_in[2];   // [8, 4096, 2048] f32
    const float* bs = (const float*)d_in[3];   // [8, 2048] f32
    float* out = (float*)d_out;                // [2048] f32

    for (int i = 0; i < LC; ++i) {
        reduce_kernel<<<32, 256>>>(i, x, bs, out);     // materialize slice i
        gemv_kernel<<<NTILES, 128>>>(i, ni, Ws);       // partials for layer i
    }
    reduce_kernel<<<32, 256>>>(LC, x, bs, out);        // final output
}

// round 9
// speedup vs baseline: 1.3936x; 1.0145x over previous
#include <cuda_runtime.h>
#include <math.h>

// Problem constants (match reference)
#define N_INPUTSC 2048
#define UNITSC    2048
#define LC        8
#define FANINC    4096
#define TOTALC    18432

#define KC      128          // k-chunks (partial-sum depth)
#define KCH     32           // rows per chunk
#define JT      4            // column tiles of 512
#define NTILES  (KC * JT)    // 512 gemv blocks per layer

// Persistent scratch (allocation-free rule: __device__ globals)
__device__ float g_partial[2][KC * UNITSC];  // ping-pong partials, 1MB each
__device__ float g_outputs[TOTALC];          // materialized state vector
__device__ float g_gather[FANINC];           // gathered input for current layer

// ---------------------------------------------------------------------------
// reduce: materialize slice `layer` = tanh(colsum(prev partials) + b) (x for
// layer 0; d_out for layer==LC). Coalesced thread-per-column.
// Block = 256 thr as (64 cols x 4 kgroups). Grid = 32 blocks.
// ---------------------------------------------------------------------------
__global__ __launch_bounds__(256) void reduce_kernel(
    int layer,
    const float* __restrict__ x,
    const float* __restrict__ bs,
    float*       __restrict__ out)
{
    const int u  = blockIdx.x * 64 + (threadIdx.x & 63);   // column 0..2047
    const int g  = threadIdx.x >> 6;                        // k-group 0..3
    const int base = layer << 11;

    if (layer == 0) {
        if (g == 0) g_outputs[u] = x[u];
        return;
    }

    const float* P = g_partial[(layer + 1) & 1] + u;        // prev partials
    float s0 = 0.f, s1 = 0.f;
#pragma unroll 8
    for (int j = 0; j < KC / 4; j += 2) {
        s0 += P[(size_t)(g * (KC / 4) + j)     * UNITSC];
        s1 += P[(size_t)(g * (KC / 4) + j + 1) * UNITSC];
    }
    __shared__ float sred[4][64];
    sred[g][threadIdx.x & 63] = s0 + s1;
    __syncthreads();
    if (g == 0) {
        float s = sred[0][u & 63] + sred[1][u & 63]
                + sred[2][u & 63] + sred[3][u & 63];
        float o = tanhf(s + bs[(layer - 1) * UNITSC + u]);
        if (layer == LC) out[u]              = o;
        else             g_outputs[base + u] = o;
    }
}

// ---------------------------------------------------------------------------
// gather: g_gather[k] = outputs[node_inds[layer][k]], 0 for not-yet-written
// slices. Pure copy; slice `layer` was just materialized by reduce.
// ---------------------------------------------------------------------------
__global__ __launch_bounds__(256) void gather_kernel(
    int layer, const int* __restrict__ node_inds)
{
    const int k = blockIdx.x * 256 + threadIdx.x;
    const int limit = (layer + 1) << 11;
    int idx = node_inds[layer * FANINC + k];
    g_gather[k] = (idx < limit) ? g_outputs[idx] : 0.f;
}

// ---------------------------------------------------------------------------
// gemv: R4's proven geometry + zero-row skip. Block = (128,4) threads.
// Block (kc, jt): rows [kc*32,+32), cols [jt*512,+512).
// Thread (tx,ty): 4 cols (float4), 8 rows (ty group). Rows whose gathered
// value is exactly 0 (unwritten future slices) skip their W load entirely —
// eliminates ~50% of DRAM traffic across the 8 layers. gk is warp-uniform
// so the branch is convergent.
// ---------------------------------------------------------------------------
__global__ __launch_bounds__(512, 2) void gemv_kernel(
    int layer,
    const float* __restrict__ Ws)
{
    float* Pcur = g_partial[layer & 1];
    const int kc = blockIdx.x >> 2;
    const int jt = blockIdx.x & 3;
    const int tx = threadIdx.x;
    const int ty = threadIdx.y;

    __shared__ float  sg[KCH];
    __shared__ float4 red[3][128];

    int tid = ty * 128 + tx;
    if (tid < KCH) sg[tid] = g_gather[kc * KCH + tid];
    __syncthreads();

    const int j0 = jt * 512 + tx * 4;
    const float* W = Ws + ((size_t)layer * FANINC + kc * KCH + ty * 8) * UNITSC + j0;

    float ax = 0.f, ay = 0.f, az = 0.f, aw = 0.f;
#pragma unroll
    for (int r = 0; r < 8; ++r) {
        float gk = sg[ty * 8 + r];
        if (gk != 0.f) {
            float4 w = *reinterpret_cast<const float4*>(W + (size_t)r * UNITSC);
            ax = fmaf(gk, w.x, ax);
            ay = fmaf(gk, w.y, ay);
            az = fmaf(gk, w.z, az);
            aw = fmaf(gk, w.w, aw);
        }
    }

    if (ty > 0) red[ty - 1][tx] = make_float4(ax, ay, az, aw);
    __syncthreads();
    if (ty == 0) {
#pragma unroll
        for (int r = 0; r < 3; ++r) {
            float4 p = red[r][tx];
            ax += p.x; ay += p.y; az += p.z; aw += p.w;
        }
        *reinterpret_cast<float4*>(Pcur + kc * UNITSC + j0) =
            make_float4(ax, ay, az, aw);
    }
}

extern "C" void kernel_launch(void* const* d_in, const int* in_sizes, int n_in,
                              void* d_out, int out_size) {
    const float* x  = (const float*)d_in[0];   // [2048] f32
    const int*   ni = (const int*)d_in[1];     // [8, 4096] i32
    const float* Ws = (const float*)d_in[2];   // [8, 4096, 2048] f32
    const float* bs = (const float*)d_in[3];   // [8, 2048] f32
    float* out = (float*)d_out;                // [2048] f32

    dim3 gemv_block(128, 4);
    for (int i = 0; i < LC; ++i) {
        reduce_kernel<<<32, 256>>>(i, x, bs, out);      // materialize slice i
        gather_kernel<<<FANINC / 256, 256>>>(i, ni);    // build g_gather
        gemv_kernel<<<NTILES, gemv_block>>>(i, Ws);     // partials, skip zeros
    }
    reduce_kernel<<<32, 256>>>(LC, x, bs, out);         // final output
}

// round 10
// speedup vs baseline: 1.6525x; 1.1858x over previous
#include <cuda_runtime.h>
#include <math.h>

// Problem constants (match reference)
#define N_INPUTSC 2048
#define UNITSC    2048
#define LC        8
#define FANINC    4096
#define TOTALC    18432

#define KC      128          // k-chunks (partial-sum depth)
#define KCH     32           // rows per chunk
#define JT      4            // column tiles of 512
#define NTILES  (KC * JT)    // 512 gemv blocks per layer

// Persistent scratch (allocation-free rule: __device__ globals)
__device__ float g_partial[2][KC * UNITSC];  // ping-pong partials, 1MB each
__device__ float g_outputs[TOTALC];          // materialized state vector

// ---------------------------------------------------------------------------
// reduce: materialize slice `layer` = tanh(colsum(prev partials) + b) (x for
// layer 0; d_out for layer==LC). Grid = 128 blocks x 256 threads.
// Block covers 16 columns; 16 k-threads per column, each summing 8 rows
// (8 independent, fully unrolled loads), then a smem combine.
// ---------------------------------------------------------------------------
__global__ __launch_bounds__(256) void reduce_kernel(
    int layer,
    const float* __restrict__ x,
    const float* __restrict__ bs,
    float*       __restrict__ out)
{
    const int cl = threadIdx.x & 15;            // column within block
    const int kt = threadIdx.x >> 4;            // k-thread 0..15
    const int u  = blockIdx.x * 16 + cl;        // column 0..2047
    const int base = layer << 11;

    if (layer == 0) {
        if (kt == 0) g_outputs[u] = x[u];
        return;
    }

    const float* P = g_partial[(layer + 1) & 1] + (size_t)(kt * 8) * UNITSC + u;
    float a0 = 0.f, a1 = 0.f, a2 = 0.f, a3 = 0.f;
#pragma unroll
    for (int j = 0; j < 8; j += 4) {
        a0 += P[(size_t)(j    ) * UNITSC];
        a1 += P[(size_t)(j + 1) * UNITSC];
        a2 += P[(size_t)(j + 2) * UNITSC];
        a3 += P[(size_t)(j + 3) * UNITSC];
    }

    __shared__ float sred[16][17];
    sred[kt][cl] = (a0 + a1) + (a2 + a3);
    __syncthreads();

    if (kt == 0) {
        float s = 0.f;
#pragma unroll
        for (int r = 0; r < 16; ++r) s += sred[r][cl];
        float o = tanhf(s + bs[(layer - 1) * UNITSC + u]);
        if (layer == LC) out[u]              = o;
        else             g_outputs[base + u] = o;
    }
}

// ---------------------------------------------------------------------------
// gemv: R9's zero-skip geometry, gather fused into the prologue.
// Block = (128,4) threads. Block (kc, jt): rows [kc*32,+32), cols [jt*512,+512).
// Prologue: 32 threads fetch sg[] = g_outputs[node_inds[...]] (0 for
// not-yet-written slices). Rows with sg==0 skip their W load entirely
// (~50% of DRAM traffic over the 8 layers; warp-uniform, convergent).
// ---------------------------------------------------------------------------
__global__ __launch_bounds__(512, 2) void gemv_kernel(
    int layer,
    const int*   __restrict__ node_inds,
    const float* __restrict__ Ws)
{
    float* Pcur = g_partial[layer & 1];
    const int kc = blockIdx.x >> 2;
    const int jt = blockIdx.x & 3;
    const int tx = threadIdx.x;
    const int ty = threadIdx.y;
    const int limit = (layer + 1) << 11;

    __shared__ float  sg[KCH];
    __shared__ float4 red[3][128];

    int tid = ty * 128 + tx;
    if (tid < KCH) {
        int idx = node_inds[layer * FANINC + kc * KCH + tid];
        sg[tid] = (idx < limit) ? g_outputs[idx] : 0.f;
    }
    __syncthreads();

    const int j0 = jt * 512 + tx * 4;
    const float* W = Ws + ((size_t)layer * FANINC + kc * KCH + ty * 8) * UNITSC + j0;

    float ax = 0.f, ay = 0.f, az = 0.f, aw = 0.f;
#pragma unroll
    for (int r = 0; r < 8; ++r) {
        float gk = sg[ty * 8 + r];
        if (gk != 0.f) {
            float4 w = *reinterpret_cast<const float4*>(W + (size_t)r * UNITSC);
            ax = fmaf(gk, w.x, ax);
            ay = fmaf(gk, w.y, ay);
            az = fmaf(gk, w.z, az);
            aw = fmaf(gk, w.w, aw);
        }
    }

    if (ty > 0) red[ty - 1][tx] = make_float4(ax, ay, az, aw);
    __syncthreads();
    if (ty == 0) {
#pragma unroll
        for (int r = 0; r < 3; ++r) {
            float4 p = red[r][tx];
            ax += p.x; ay += p.y; az += p.z; aw += p.w;
        }
        *reinterpret_cast<float4*>(Pcur + kc * UNITSC + j0) =
            make_float4(ax, ay, az, aw);
    }
}

extern "C" void kernel_launch(void* const* d_in, const int* in_sizes, int n_in,
                              void* d_out, int out_size) {
    const float* x  = (const float*)d_in[0];   // [2048] f32
    const int*   ni = (const int*)d_in[1];     // [8, 4096] i32
    const float* Ws = (const float*)d_in[2];   // [8, 4096, 2048] f32
    const float* bs = (const float*)d_in[3];   // [8, 2048] f32
    float* out = (float*)d_out;                // [2048] f32

    dim3 gemv_block(128, 4);
    for (int i = 0; i < LC; ++i) {
        reduce_kernel<<<128, 256>>>(i, x, bs, out);     // materialize slice i
        gemv_kernel<<<NTILES, gemv_block>>>(i, ni, Ws); // partials, skip zeros
    }
    reduce_kernel<<<128, 256>>>(LC, x, bs, out);        // final output
}

// round 11
// speedup vs baseline: 2.0225x; 1.2239x over previous
#include <cuda_runtime.h>
#include <math.h>

// Problem constants (match reference)
#define N_INPUTSC 2048
#define UNITSC    2048
#define LC        8
#define FANINC    4096
#define TOTALC    18432

#define KC      32            // partial-sum depth (k-chunks of 128 rows)
#define RPC     128           // rows per chunk
#define JT      16            // column tiles of 128
#define CPB     128           // cols per tile
#define GEMV_BLOCKS (KC * JT) // 512
#define MAT_BLOCKS  8         // materialization blocks appended to the grid

// Persistent scratch (allocation-free rule: __device__ globals)
__device__ float g_partial[2][KC * UNITSC];  // ping-pong partials, 256KB each
__device__ float g_outputs[TOTALC];          // materialized state vector

// Sum the KC partials for column u of the previous layer (coalesced across
// consecutive-u threads; L2-resident).
__device__ __forceinline__ float sum_partials(const float* __restrict__ P, int u) {
    float s0 = 0.f, s1 = 0.f;
#pragma unroll
    for (int c = 0; c < KC; c += 2) {
        s0 += P[(size_t)c       * UNITSC + u];
        s1 += P[(size_t)(c + 1) * UNITSC + u];
    }
    return s0 + s1;
}

// ---------------------------------------------------------------------------
// fused layer kernel, one launch per layer.
//  - blocks [0, 512): gemv. Block (kc, jt): rows [kc*128,+128), cols
//    [jt*128,+128). Prologue: 128 threads gather one element each
//    (old slices -> g_outputs; current slice -> recompute from prev partials;
//    future -> 0). Main: 8 warps x 16 rows x 128 cols, zero rows skip their
//    W load (convergent, ~50% of DRAM traffic saved across layers).
//  - blocks [512, 520): materialize slice `layer` into g_outputs for use by
//    layers >= layer+1 (concurrent with gemv; no reader this launch).
// ---------------------------------------------------------------------------
__global__ __launch_bounds__(256) void layer_kernel(
    int layer,
    const float* __restrict__ x,
    const int*   __restrict__ node_inds,
    const float* __restrict__ Ws,
    const float* __restrict__ bs)
{
    const int tid  = threadIdx.x;
    const int base = layer << 11;
    const float* Pprev = g_partial[(layer + 1) & 1];
    const float* bprev = bs + (layer - 1) * UNITSC;

    if (blockIdx.x >= GEMV_BLOCKS) {
        // ---- materialize slice `layer` ----
        int u = (blockIdx.x - GEMV_BLOCKS) * 256 + tid;
        float o;
        if (layer == 0) o = x[u];
        else            o = tanhf(sum_partials(Pprev, u) + bprev[u]);
        g_outputs[base + u] = o;
        return;
    }

    const int kc = blockIdx.x >> 4;
    const int jt = blockIdx.x & 15;

    __shared__ float  sg[RPC];
    __shared__ float4 red[8][32];

    // Prologue: one gather element per thread (first 128 threads).
    if (tid < RPC) {
        int idx = node_inds[layer * FANINC + kc * RPC + tid];
        float v = 0.f;
        if (idx < base) {
            v = g_outputs[idx];                  // older slice, materialized
        } else if (idx < base + UNITSC) {
            int u = idx - base;                  // current slice: recompute
            if (layer == 0) v = x[u];
            else            v = tanhf(sum_partials(Pprev, u) + bprev[u]);
        }
        sg[tid] = v;
    }
    __syncthreads();

    const int tx = tid & 31;
    const int tg = tid >> 5;                     // warp id: 16 rows each
    const float* W = Ws + ((size_t)layer * FANINC + kc * RPC + tg * 16) * UNITSC
                   + jt * CPB + tx * 4;

    float ax = 0.f, ay = 0.f, az = 0.f, aw = 0.f;
#pragma unroll
    for (int r = 0; r < 16; ++r) {
        float gk = sg[tg * 16 + r];
        if (gk != 0.f) {                         // warp-uniform skip
            float4 w = *reinterpret_cast<const float4*>(W + (size_t)r * UNITSC);
            ax = fmaf(gk, w.x, ax);
            ay = fmaf(gk, w.y, ay);
            az = fmaf(gk, w.z, az);
            aw = fmaf(gk, w.w, aw);
        }
    }

    red[tg][tx] = make_float4(ax, ay, az, aw);
    __syncthreads();
    if (tg == 0) {
        float4 s = red[0][tx];
#pragma unroll
        for (int r = 1; r < 8; ++r) {
            float4 p = red[r][tx];
            s.x += p.x; s.y += p.y; s.z += p.z; s.w += p.w;
        }
        *reinterpret_cast<float4*>(g_partial[layer & 1]
                                   + kc * UNITSC + jt * CPB + tx * 4) = s;
    }
}

// ---------------------------------------------------------------------------
// final: out = tanh(colsum(layer-7 partials) + b7)
// ---------------------------------------------------------------------------
__global__ __launch_bounds__(256) void final_kernel(
    const float* __restrict__ bs, float* __restrict__ out)
{
    int u = blockIdx.x * 256 + threadIdx.x;
    const float* P = g_partial[(LC - 1) & 1];
    out[u] = tanhf(sum_partials(P, u) + bs[(LC - 1) * UNITSC + u]);
}

extern "C" void kernel_launch(void* const* d_in, const int* in_sizes, int n_in,
                              void* d_out, int out_size) {
    const float* x  = (const float*)d_in[0];   // [2048] f32
    const int*   ni = (const int*)d_in[1];     // [8, 4096] i32
    const float* Ws = (const float*)d_in[2];   // [8, 4096, 2048] f32
    const float* bs = (const float*)d_in[3];   // [8, 2048] f32
    float* out = (float*)d_out;                // [2048] f32

    for (int i = 0; i < LC; ++i) {
        layer_kernel<<<GEMV_BLOCKS + MAT_BLOCKS, 256>>>(i, x, ni, Ws, bs);
    }
    final_kernel<<<UNITSC / 256, 256>>>(bs, out);
}